// round 4
// baseline (speedup 1.0000x reference)
#include <cuda_runtime.h>
#include <cuda_bf16.h>

// Wav2Frames: out[b, c, f] = x[b, f*WINSTEP + c]
// x: (32, 1, 480000) fp32 -> out: (32, 400, 2998) fp32
//
// R4: persistent CTAs + double-buffered smem software pipeline.
//   grid = 444 (=148*3) CTAs over 3008 flattened (b,tile) jobs, tile-major.
//   per job: LDG(next tile)->regs issued FIRST, drain(cur) from smem
//   (covers the LDG latency with LDS/STG work), STS(next) -> other buffer,
//   one __syncthreads(). Read & write DRAM streams stay concurrently active.

#define B        32
#define T        480000
#define WINLEN   400
#define WINSTEP  160
#define NFRAMES  2998
#define F_TILE   32
#define NTILES   94                                   // ceil(2998/32)
#define SPAN     ((F_TILE - 1) * WINSTEP + WINLEN)    // 5360 floats
#define SPAN4    (SPAN / 4)                           // 1340
#define SM_SZ    (SPAN + 2 * (SPAN >> 6) + 8)         // 5534 floats (~22.1KB)
#define NJOBS    (B * NTILES)                         // 3008
#define NCTAS    444                                  // 148 SMs * 3 CTAs
#define THREADS  512

__device__ __forceinline__ int skew(int j) { return j + 2 * (j >> 6); }

__global__ __launch_bounds__(THREADS, 3)
void wav2frames_kernel(const float* __restrict__ x, float* __restrict__ out) {
    __shared__ float sm[2][SM_SZ];

    const int tid  = threadIdx.x;
    const int lane = tid & 31;
    const int w    = tid >> 5;                        // 16 warps
    // fill-side lane permutation (swap bits 3<->4): conflict-free STS.64
    const int sig    = (lane & 7) | ((lane & 8) << 1) | ((lane & 16) >> 1);
    const int i4base = w * 32 + sig;                  // + round*512
    // drain-side decomposition
    const int k = lane & 15;                          // frame pair index
    const int h = lane >> 4;                          // c sub-pair

    int job  = blockIdx.x;
    int b    = job / NTILES;
    int tile = job - b * NTILES;

    float4 r0, r1, r2;
    int    span4;

    // ---- prolog: load + stage job0 into buffer 0 ----
    {
        const int x0 = tile * F_TILE * WINSTEP;
        span4 = (((x0 + SPAN <= T) ? SPAN : (T - x0)) >> 2);
        const float4* __restrict__ src =
            reinterpret_cast<const float4*>(x + (size_t)b * T + x0);
        if (i4base          < span4) r0 = src[i4base];
        if (i4base + 512    < span4) r1 = src[i4base + 512];
        if (i4base + 1024   < span4) r2 = src[i4base + 1024];

        if (i4base < span4) {
            const int p = skew(4 * i4base);
            *reinterpret_cast<float2*>(&sm[0][p])     = make_float2(r0.x, r0.y);
            *reinterpret_cast<float2*>(&sm[0][p + 2]) = make_float2(r0.z, r0.w);
        }
        if (i4base + 512 < span4) {
            const int p = skew(4 * (i4base + 512));
            *reinterpret_cast<float2*>(&sm[0][p])     = make_float2(r1.x, r1.y);
            *reinterpret_cast<float2*>(&sm[0][p + 2]) = make_float2(r1.z, r1.w);
        }
        if (i4base + 1024 < span4) {
            const int p = skew(4 * (i4base + 1024));
            *reinterpret_cast<float2*>(&sm[0][p])     = make_float2(r2.x, r2.y);
            *reinterpret_cast<float2*>(&sm[0][p + 2]) = make_float2(r2.z, r2.w);
        }
    }
    __syncthreads();

    int buf = 0;
    for (;;) {
        const int  njob      = job + NCTAS;
        const bool have_next = (njob < NJOBS);
        int nb = 0, ntile = 0, nspan4 = 0;

        // ---- issue next tile's LDGs early (fills MLP during drain) ----
        if (have_next) {
            nb    = njob / NTILES;
            ntile = njob - nb * NTILES;
            const int x0 = ntile * F_TILE * WINSTEP;
            nspan4 = (((x0 + SPAN <= T) ? SPAN : (T - x0)) >> 2);
            const float4* __restrict__ src =
                reinterpret_cast<const float4*>(x + (size_t)nb * T + x0);
            if (i4base        < nspan4) r0 = src[i4base];
            if (i4base + 512  < nspan4) r1 = src[i4base + 512];
            if (i4base + 1024 < nspan4) r2 = src[i4base + 1024];
        }

        // ---- drain current tile: smem -> gmem (covers the LDG latency) ----
        {
            const float* __restrict__ bufp = sm[buf];
            const int f0 = tile * F_TILE;
            const int fp = f0 + 2 * k;
            const bool fp_ok = (fp <= NFRAMES - 2);
            float* __restrict__ op =
                out + ((size_t)b * WINLEN + 2 * h) * NFRAMES + fp;

            #pragma unroll 4
            for (int cq = w; cq < WINLEN / 4; cq += 16) {   // 6-7 iters
                const int c  = 4 * cq;                       // + 2h -> column
                const int j0 = 320 * k + c + 2 * h;
                const float2 a =
                    *reinterpret_cast<const float2*>(bufp + skew(j0));
                const float2 d =
                    *reinterpret_cast<const float2*>(bufp + skew(j0 + WINSTEP));
                if (fp_ok) {
                    *reinterpret_cast<float2*>(op + (size_t)c * NFRAMES) =
                        make_float2(a.x, d.x);
                    *reinterpret_cast<float2*>(op + (size_t)(c + 1) * NFRAMES) =
                        make_float2(a.y, d.y);
                }
            }
        }

        // ---- stage next tile into the other buffer ----
        if (have_next) {
            float* __restrict__ dst = sm[buf ^ 1];
            if (i4base < nspan4) {
                const int p = skew(4 * i4base);
                *reinterpret_cast<float2*>(&dst[p])     = make_float2(r0.x, r0.y);
                *reinterpret_cast<float2*>(&dst[p + 2]) = make_float2(r0.z, r0.w);
            }
            if (i4base + 512 < nspan4) {
                const int p = skew(4 * (i4base + 512));
                *reinterpret_cast<float2*>(&dst[p])     = make_float2(r1.x, r1.y);
                *reinterpret_cast<float2*>(&dst[p + 2]) = make_float2(r1.z, r1.w);
            }
            if (i4base + 1024 < nspan4) {
                const int p = skew(4 * (i4base + 1024));
                *reinterpret_cast<float2*>(&dst[p])     = make_float2(r2.x, r2.y);
                *reinterpret_cast<float2*>(&dst[p + 2]) = make_float2(r2.z, r2.w);
            }
        }
        __syncthreads();

        if (!have_next) break;
        job = njob; b = nb; tile = ntile; buf ^= 1;
    }
}

extern "C" void kernel_launch(void* const* d_in, const int* in_sizes, int n_in,
                              void* d_out, int out_size) {
    const float* x = (const float*)d_in[0];            // (32, 1, 480000) fp32
    // d_in[1] = W (identity, unused), d_in[2] = winstep (fixed 160, unused)
    float* out = (float*)d_out;                        // (32, 400, 2998) fp32

    wav2frames_kernel<<<NCTAS, THREADS>>>(x, out);
}

// round 5
// speedup vs baseline: 1.3131x; 1.3131x over previous
#include <cuda_runtime.h>
#include <cuda_bf16.h>

// Wav2Frames: out[b, c, f] = x[b, f*WINSTEP + c]
// (conv1d with identity eye(400) kernel, stride 160, VALID padding)
// x: (32, 1, 480000) fp32 -> out: (32, 400, 2998) fp32
//
// R5 = R2 access pattern scaled up:
//  - F_TILE 64 -> 128 via DYNAMIC smem (~85 KB), block 512 -> 1024 threads
//    -> 2 CTAs/SM (170 KB smem, 2048 threads) = 100% theoretical occupancy
//  - store segments per row grow 256B -> 512B (fewer partial sectors)
//  - read overlap halves (240/20720 = 1.2%)
//  - same skew j + (j>>5); float4 LDG fill; float2 frame-pair STG;
//    2-way LDS conflict tolerated (proven fastest in R2 vs "fixed" R3).

#define B        32
#define T        480000
#define WINLEN   400
#define WINSTEP  160
#define NFRAMES  2998
#define F_TILE   128
#define NTILES   ((NFRAMES + F_TILE - 1) / F_TILE)    // 24
#define SPAN     ((F_TILE - 1) * WINSTEP + WINLEN)    // 20720 floats
#define SM_SZ    (SPAN + SPAN / 32 + 4)               // 21371 floats (~85.5 KB)
#define THREADS  1024

__global__ __launch_bounds__(THREADS, 2)
void wav2frames_kernel(const float* __restrict__ x, float* __restrict__ out) {
    extern __shared__ float sm[];

    const int tile = blockIdx.x;
    const int b    = blockIdx.y;
    const int tid  = threadIdx.x;
    const int lane = tid & 31;
    const int w    = tid >> 5;                        // 32 warps

    const int f0 = tile * F_TILE;
    const int x0 = f0 * WINSTEP;                      // multiple of 4 -> 16B aligned

    // ---- vectorized coalesced fill: gmem float4 -> skewed smem ----
    const float* __restrict__ xb = x + (size_t)b * T + x0;
    const int span  = (x0 + SPAN <= T) ? SPAN : (T - x0);   // multiple of 4
    const int span4 = span >> 2;
    const float4* __restrict__ xb4 = reinterpret_cast<const float4*>(xb);

    for (int i4 = tid; i4 < span4; i4 += THREADS) {   // ~5 iterations
        const float4 v = xb4[i4];
        const int i = i4 << 2;
        const int p = i + (i >> 5);                   // skew: j + (j>>5)
        sm[p + 0] = v.x;
        sm[p + 1] = v.y;
        sm[p + 2] = v.z;
        sm[p + 3] = v.w;
    }
    __syncthreads();

    // ---- store: 64 frame pairs x 16 c-groups ----
    // warp's lanes hold consecutive frame pairs at fixed c -> 256B coalesced STG
    const int q      = w & 1;                         // frame-pair half
    const int cg     = w >> 1;                        // c-group 0..15
    const int fp_idx = lane + 32 * q;                 // 0..63
    const int fp     = f0 + 2 * fp_idx;

    if (fp < NFRAMES - 1) {                           // pairs never split (even)
        float2* __restrict__ ob =
            reinterpret_cast<float2*>(out + (size_t)b * WINLEN * NFRAMES + fp);
        const int jb = fp_idx * (2 * WINSTEP);        // 320 * fp_idx

        #pragma unroll 5
        for (int c = cg; c < WINLEN; c += 16) {       // 25 iterations
            const int j0 = jb + c;
            const int j1 = j0 + WINSTEP;
            float2 v;
            v.x = sm[j0 + (j0 >> 5)];
            v.y = sm[j1 + (j1 >> 5)];
            ob[(size_t)c * (NFRAMES / 2)] = v;
        }
    }
}

extern "C" void kernel_launch(void* const* d_in, const int* in_sizes, int n_in,
                              void* d_out, int out_size) {
    const float* x = (const float*)d_in[0];           // (32, 1, 480000) fp32
    // d_in[1] = W (identity, unused), d_in[2] = winstep (fixed 160, unused)
    float* out = (float*)d_out;                       // (32, 400, 2998) fp32

    static bool configured = false;
    if (!configured) {
        cudaFuncSetAttribute(wav2frames_kernel,
                             cudaFuncAttributeMaxDynamicSharedMemorySize,
                             SM_SZ * (int)sizeof(float));
        configured = true;
    }

    dim3 grid(NTILES, B);                             // 24 x 32 = 768 CTAs
    wav2frames_kernel<<<grid, THREADS, SM_SZ * sizeof(float)>>>(x, out);
}

// round 6
// speedup vs baseline: 1.3850x; 1.0548x over previous
#include <cuda_runtime.h>
#include <cuda_bf16.h>

// Wav2Frames: out[b, c, f] = x[b, f*WINSTEP + c]
// x: (32, 1, 480000) fp32 -> out: (32, 400, 2998) fp32
//
// R6 = R5 + sector-aligned per-row shifted frame partition.
//   Row byte base 11992*c mod 32 = 24c, so fixed-f0 chunks straddle sectors.
//   Shift each row's chunk by s(c) = (2c)&7 frames so every chunk start is
//   32B-aligned: 24c + 4*s(c) mod 32 == 0 for all c. Chunks = exactly
//   sector-aligned 512B spans -> no partial-sector (ECC RMW) writes.
//   Tile 0 writes the per-row head [0, s(c)); tail guarded by f <= 2996.

#define B        32
#define T        480000
#define WINLEN   400
#define WINSTEP  160
#define NFRAMES  2998
#define F_TILE   128
#define NTILES   24                                   // covers 3072+s >= 2998
#define SPAN     ((F_TILE - 1) * WINSTEP + WINLEN + 6 * WINSTEP)  // 21680
#define SM_SZ    (SPAN + SPAN / 32 + 4)               // 22361 floats (~89.4 KB)
#define THREADS  1024

__global__ __launch_bounds__(THREADS, 2)
void wav2frames_kernel(const float* __restrict__ x, float* __restrict__ out) {
    extern __shared__ float sm[];

    const int tile = blockIdx.x;
    const int b    = blockIdx.y;
    const int tid  = threadIdx.x;
    const int lane = tid & 31;
    const int w    = tid >> 5;                        // 32 warps

    const int f0 = tile * F_TILE;                     // multiple of 128
    const int x0 = f0 * WINSTEP;

    // ---- vectorized coalesced fill: gmem float4 -> skewed smem ----
    const float* __restrict__ xb = x + (size_t)b * T + x0;
    const int span  = (x0 + SPAN <= T) ? SPAN : (T - x0);   // multiple of 4
    const int span4 = span >> 2;
    const float4* __restrict__ xb4 = reinterpret_cast<const float4*>(xb);

    for (int i4 = tid; i4 < span4; i4 += THREADS) {   // ~6 iterations
        const float4 v = xb4[i4];
        const int i = i4 << 2;
        const int p = i + (i >> 5);                   // skew: j + (j>>5)
        sm[p + 0] = v.x;
        sm[p + 1] = v.y;
        sm[p + 2] = v.z;
        sm[p + 3] = v.w;
    }
    __syncthreads();

    float* __restrict__ outb = out + (size_t)b * WINLEN * NFRAMES;

    // ---- main store: 64 frame pairs x 16 c-groups, per-row shift s(c) ----
    const int q      = w & 1;
    const int cg     = w >> 1;                        // 0..15
    const int fp_idx = lane + 32 * q;                 // 0..63
    const int fbase  = f0 + 2 * fp_idx;               // even
    const int jbase  = 2 * fp_idx * WINSTEP;          // 320 * fp_idx

    #pragma unroll 5
    for (int c = cg; c < WINLEN; c += 16) {           // 25 iterations
        const int s = (2 * c) & 7;                    // 0,2,4,6 (even)
        const int f = fbase + s;
        if (f <= NFRAMES - 2) {
            const int j0 = jbase + s * WINSTEP + c;
            const int j1 = j0 + WINSTEP;
            float2 v;
            v.x = sm[j0 + (j0 >> 5)];
            v.y = sm[j1 + (j1 >> 5)];
            *reinterpret_cast<float2*>(outb + (size_t)c * NFRAMES + f) = v;
        }
    }

    // ---- head: tile 0 writes frames [0, s(c)) for each row c ----
    if (tile == 0) {
        for (int idx = tid; idx < WINLEN * 3; idx += THREADS) {
            const int c = idx / 3;
            const int m = idx - 3 * c;                // pair slot 0..2
            const int s = (2 * c) & 7;
            if (2 * m < s) {
                const int f  = 2 * m;
                const int j0 = f * WINSTEP + c;
                const int j1 = j0 + WINSTEP;
                float2 v;
                v.x = sm[j0 + (j0 >> 5)];
                v.y = sm[j1 + (j1 >> 5)];
                *reinterpret_cast<float2*>(outb + (size_t)c * NFRAMES + f) = v;
            }
        }
    }
}

extern "C" void kernel_launch(void* const* d_in, const int* in_sizes, int n_in,
                              void* d_out, int out_size) {
    const float* x = (const float*)d_in[0];           // (32, 1, 480000) fp32
    // d_in[1] = W (identity, unused), d_in[2] = winstep (fixed 160, unused)
    float* out = (float*)d_out;                       // (32, 400, 2998) fp32

    static bool configured = false;
    if (!configured) {
        cudaFuncSetAttribute(wav2frames_kernel,
                             cudaFuncAttributeMaxDynamicSharedMemorySize,
                             SM_SZ * (int)sizeof(float));
        configured = true;
    }

    dim3 grid(NTILES, B);                             // 24 x 32 = 768 CTAs
    wav2frames_kernel<<<grid, THREADS, SM_SZ * sizeof(float)>>>(x, out);
}